// round 6
// baseline (speedup 1.0000x reference)
#include <cuda_runtime.h>

// out[b, l, i, j] = emission[b, l, j] + transition[i, j]
// B=32, L=512, T=64. Output = 256 MB fp32, HBM-write-bound (~5.1 TB/s plateau).
//
// Persistent single-wave grid (592 blocks = 148 SMs x 4 resident blocks of
// 512 threads) to eliminate wave-transition DRAM-idle bubbles.
// Thread t owns (i = t>>3, j8 = t&7); transition[i, j8*8..] register-resident,
// loaded once per block (amortized over ~28 rows). Grid-stride over chunks of
// 8 (b,l) rows; per row: one emission v8 load (broadcast, 2 L1 wavefronts/warp)
// + one v8 .cs store (1KB contiguous per warp).

__device__ __forceinline__ void ldg256(const float* p, float4& a, float4& b) {
    asm volatile("ld.global.nc.v8.f32 {%0,%1,%2,%3,%4,%5,%6,%7}, [%8];"
                 : "=f"(a.x), "=f"(a.y), "=f"(a.z), "=f"(a.w),
                   "=f"(b.x), "=f"(b.y), "=f"(b.z), "=f"(b.w)
                 : "l"(p));
}

__device__ __forceinline__ void stg256_cs(float* p, float4 a, float4 b) {
    asm volatile("st.global.cs.v8.f32 [%0], {%1,%2,%3,%4,%5,%6,%7,%8};"
                 :: "l"(p),
                    "f"(a.x), "f"(a.y), "f"(a.z), "f"(a.w),
                    "f"(b.x), "f"(b.y), "f"(b.z), "f"(b.w)
                 : "memory");
}

#define ROWS_PER_CHUNK 8
#define N_CHUNKS 2048            // 16384 rows / 8
#define GRID_BLOCKS 592          // 148 SMs * 4 resident blocks -> one wave

__global__ __launch_bounds__(512)
void CRF_53128745451552_kernel(const float* __restrict__ em,
                               const float* __restrict__ tr,
                               float* __restrict__ out) {
    int t  = threadIdx.x;
    int j8 = t & 7;     // j chunk (8 floats)
    int i  = t >> 3;    // 0..63

    // Transition chunk for this (i, j8): loaded once, register-resident.
    float4 t0, t1;
    ldg256(tr + (i << 6) + (j8 << 3), t0, t1);

    const int ioff = (i << 6) + (j8 << 3);
    const int joff = (j8 << 3);

    for (int chunk = blockIdx.x; chunk < N_CHUNKS; chunk += GRID_BLOCKS) {
        size_t bl0 = (size_t)chunk * ROWS_PER_CHUNK;
        const float* ep = em  + (bl0 << 6)  + joff;
        float*       op = out + (bl0 << 12) + ioff;

#pragma unroll
        for (int r = 0; r < ROWS_PER_CHUNK; r += 2) {
            float4 ea0, ea1, eb0, eb1;
            ldg256(ep + (size_t)r * 64,       ea0, ea1);
            ldg256(ep + (size_t)(r + 1) * 64, eb0, eb1);

            float4 r0, r1;
            r0.x = ea0.x + t0.x;  r0.y = ea0.y + t0.y;
            r0.z = ea0.z + t0.z;  r0.w = ea0.w + t0.w;
            r1.x = ea1.x + t1.x;  r1.y = ea1.y + t1.y;
            r1.z = ea1.z + t1.z;  r1.w = ea1.w + t1.w;
            stg256_cs(op + (size_t)r * 4096, r0, r1);

            float4 s0, s1;
            s0.x = eb0.x + t0.x;  s0.y = eb0.y + t0.y;
            s0.z = eb0.z + t0.z;  s0.w = eb0.w + t0.w;
            s1.x = eb1.x + t1.x;  s1.y = eb1.y + t1.y;
            s1.z = eb1.z + t1.z;  s1.w = eb1.w + t1.w;
            stg256_cs(op + (size_t)(r + 1) * 4096, s0, s1);
        }
    }
}

extern "C" void kernel_launch(void* const* d_in, const int* in_sizes, int n_in,
                              void* d_out, int out_size) {
    const float* em = (const float*)d_in[0];   // emission [32, 512, 64] fp32
    const float* tr = (const float*)d_in[1];   // transition [64, 64] fp32
    float* out = (float*)d_out;

    CRF_53128745451552_kernel<<<GRID_BLOCKS, 512>>>(em, tr, out);
}

// round 7
// speedup vs baseline: 1.1250x; 1.1250x over previous
#include <cuda_runtime.h>

// out[b, l, i, j] = emission[b, l, j] + transition[i, j]
// B=32, L=512, T=64. Output = 256 MB fp32 — pure HBM-write-bound,
// measured plateau ~6.1 TB/s actual write traffic (~76% of spec).
//
// Block = 256 threads. Thread t owns (i = t>>3 and i+32, j8 = t&7):
// 2 transition v8 chunks register-resident (loaded once per block).
// Each block handles 8 consecutive (b,l) rows; per row each thread does
// ONE emission v8 load (8 distinct 32B segments per warp, broadcast across
// i -> 2 L1 wavefronts) and TWO v8 .cs stores (each warp-store 1KB
// contiguous). Load:store L1 wavefront ratio 0.125:1.
// Grid = 2048 blocks (2.8 waves @ ~740 resident) — oversubscription smooths
// per-SM imbalance (persistent single-wave measured slower).

__device__ __forceinline__ void ldg256(const float* p, float4& a, float4& b) {
    asm volatile("ld.global.nc.v8.f32 {%0,%1,%2,%3,%4,%5,%6,%7}, [%8];"
                 : "=f"(a.x), "=f"(a.y), "=f"(a.z), "=f"(a.w),
                   "=f"(b.x), "=f"(b.y), "=f"(b.z), "=f"(b.w)
                 : "l"(p));
}

__device__ __forceinline__ void stg256_cs(float* p, float4 a, float4 b) {
    asm volatile("st.global.cs.v8.f32 [%0], {%1,%2,%3,%4,%5,%6,%7,%8};"
                 :: "l"(p),
                    "f"(a.x), "f"(a.y), "f"(a.z), "f"(a.w),
                    "f"(b.x), "f"(b.y), "f"(b.z), "f"(b.w)
                 : "memory");
}

#define ROWS_PER_BLOCK 8

__global__ __launch_bounds__(256)
void CRF_53128745451552_kernel(const float* __restrict__ em,
                               const float* __restrict__ tr,
                               float* __restrict__ out) {
    int t  = threadIdx.x;
    int j8 = t & 7;      // j chunk (8 floats)
    int i0 = t >> 3;     // 0..31; thread also covers i0+32

    // Two transition chunks register-resident: rows i0 and i0+32.
    float4 ta0, ta1, tb0, tb1;
    ldg256(tr + (i0 << 6)        + (j8 << 3), ta0, ta1);
    ldg256(tr + ((i0 + 32) << 6) + (j8 << 3), tb0, tb1);

    size_t bl0 = (size_t)blockIdx.x * ROWS_PER_BLOCK;
    const float* ep = em  + (bl0 << 6)  + (j8 << 3);
    float*       oa = out + (bl0 << 12) + (i0 << 6) + (j8 << 3);
    float*       ob = oa + (32 << 6);   // i0+32 rows

#pragma unroll
    for (int r = 0; r < ROWS_PER_BLOCK; r++) {
        float4 e0, e1;
        ldg256(ep + (size_t)r * 64, e0, e1);   // emission[bl0+r, j8*8..] (broadcast)

        float4 r0, r1;
        r0.x = e0.x + ta0.x;  r0.y = e0.y + ta0.y;
        r0.z = e0.z + ta0.z;  r0.w = e0.w + ta0.w;
        r1.x = e1.x + ta1.x;  r1.y = e1.y + ta1.y;
        r1.z = e1.z + ta1.z;  r1.w = e1.w + ta1.w;
        stg256_cs(oa + (size_t)r * 4096, r0, r1);

        float4 s0, s1;
        s0.x = e0.x + tb0.x;  s0.y = e0.y + tb0.y;
        s0.z = e0.z + tb0.z;  s0.w = e0.w + tb0.w;
        s1.x = e1.x + tb1.x;  s1.y = e1.y + tb1.y;
        s1.z = e1.z + tb1.z;  s1.w = e1.w + tb1.w;
        stg256_cs(ob + (size_t)r * 4096, s0, s1);
    }
}

extern "C" void kernel_launch(void* const* d_in, const int* in_sizes, int n_in,
                              void* d_out, int out_size) {
    const float* em = (const float*)d_in[0];   // emission [32, 512, 64] fp32
    const float* tr = (const float*)d_in[1];   // transition [64, 64] fp32
    float* out = (float*)d_out;

    // 16384 rows / 8 rows-per-block = 2048 blocks of 256 threads.
    CRF_53128745451552_kernel<<<2048, 256>>>(em, tr, out);
}

// round 8
// speedup vs baseline: 1.1779x; 1.0471x over previous
#include <cuda_runtime.h>

// out[b, l, i, j] = emission[b, l, j] + transition[i, j]
// B=32, L=512, T=64. Output = 256 MB fp32 — pure HBM-write-bound.
// Measured write ceiling ~6.4 TB/s (80% of spec); kernel is at that ceiling.
//
// Body = R3 winner: one warp per (b,l) row. Lane: j8 = lane&7, igrp = lane>>3.
// Emission chunk register-resident (loaded once, reused 16x); 16 iterations
// over transition rows (L1-resident), each storing 1KB contiguous per warp
// with v8 .cs stores.
// Launch shape refined: 128-thread blocks x 4096 blocks (vs 256x2048) —
// halves the scheduling tail quantum of the final partial wave.

__device__ __forceinline__ void ldg256(const float* p, float4& a, float4& b) {
    asm volatile("ld.global.nc.v8.f32 {%0,%1,%2,%3,%4,%5,%6,%7}, [%8];"
                 : "=f"(a.x), "=f"(a.y), "=f"(a.z), "=f"(a.w),
                   "=f"(b.x), "=f"(b.y), "=f"(b.z), "=f"(b.w)
                 : "l"(p));
}

__device__ __forceinline__ void stg256_cs(float* p, float4 a, float4 b) {
    asm volatile("st.global.cs.v8.f32 [%0], {%1,%2,%3,%4,%5,%6,%7,%8};"
                 :: "l"(p),
                    "f"(a.x), "f"(a.y), "f"(a.z), "f"(a.w),
                    "f"(b.x), "f"(b.y), "f"(b.z), "f"(b.w)
                 : "memory");
}

__global__ __launch_bounds__(128)
void CRF_53128745451552_kernel(const float* __restrict__ em,
                               const float* __restrict__ tr,
                               float* __restrict__ out) {
    int warp = (blockIdx.x * blockDim.x + threadIdx.x) >> 5;  // = bl, 0..16383
    int lane = threadIdx.x & 31;
    int j8   = lane & 7;    // 8-float chunk within j (0..7)
    int igrp = lane >> 3;   // i offset within a 4-row group (0..3)

    // Emission chunk for this (bl, j8): loaded once, reused 16x.
    float4 e0, e1;
    ldg256(em + ((size_t)warp << 6) + (j8 << 3), e0, e1);

    const float* tp = tr  + (igrp << 6) + (j8 << 3);
    float*       op = out + ((size_t)warp << 12) + (igrp << 6) + (j8 << 3);

#pragma unroll 4
    for (int it = 0; it < 16; it++) {
        float4 t0, t1;
        ldg256(tp + it * 256, t0, t1);   // transition[it*4+igrp, j8*8..] (L1 hit)

        float4 r0, r1;
        r0.x = e0.x + t0.x;  r0.y = e0.y + t0.y;
        r0.z = e0.z + t0.z;  r0.w = e0.w + t0.w;
        r1.x = e1.x + t1.x;  r1.y = e1.y + t1.y;
        r1.z = e1.z + t1.z;  r1.w = e1.w + t1.w;

        stg256_cs(op + it * 256, r0, r1);  // warp-iter: 1KB contiguous
    }
}

extern "C" void kernel_launch(void* const* d_in, const int* in_sizes, int n_in,
                              void* d_out, int out_size) {
    const float* em = (const float*)d_in[0];   // emission [32, 512, 64] fp32
    const float* tr = (const float*)d_in[1];   // transition [64, 64] fp32
    float* out = (float*)d_out;

    // 16384 rows, one warp each; 128 threads = 4 warps per block -> 4096 blocks.
    CRF_53128745451552_kernel<<<4096, 128>>>(em, tr, out);
}